// round 6
// baseline (speedup 1.0000x reference)
#include <cuda_runtime.h>
#include <math.h>

#define HN   256
#define CINN 39
#define BN   128
#define SEQN 200
#define TN   1000
#define ON   61

// ---------------- scratch (device globals; no allocation allowed) ----------------
__device__ float g_Xp[2][SEQN][BN][HN];        // per-frame input projection + bi (NOT br)
__device__ float g_WrT[2][257][HN];            // WrT[d][i][h] = Wr_d[h][i]; row 256 = zeros
__device__ float g_block[SEQN][BN][2 * HN];    // 5-step block averages (merged fw|bw)
__device__ float g_y[SEQN][BN][ON];            // output-head pre/post scan values
__device__ float4 g_WoutT[128][64];            // W_out k-major: [kq][o] float4; o=61..63 zero

// ---------------- 1) input projection ----------------
__global__ void __launch_bounds__(256) proj_kernel(
    const float* __restrict__ x,
    const float* __restrict__ Wi_fw, const float* __restrict__ bi_fw,
    const float* __restrict__ Wi_bw, const float* __restrict__ bi_bw)
{
    int blk = blockIdx.x;          // 0..399
    int d = blk & 1;
    int f = blk >> 1;
    const float* Wi = d ? Wi_bw : Wi_fw;
    const float* bi = d ? bi_bw : bi_fw;
    int h = threadIdx.x;

    __shared__ float xs[BN][CINN + 1];
    for (int i = h; i < BN * CINN; i += blockDim.x) {
        int b = i / CINN, c = i % CINN;
        xs[b][c] = x[(b * SEQN + f) * CINN + c];
    }
    __syncthreads();

    float w[CINN];
#pragma unroll
    for (int c = 0; c < CINN; c++) w[c] = Wi[h * CINN + c];
    float bias = bi[h];

    for (int b = 0; b < BN; b += 4) {
        float s0 = 0.0f, s1 = 0.0f, s2 = 0.0f, s3 = 0.0f;
#pragma unroll
        for (int c = 0; c < CINN; c++) {
            float wc = w[c];
            s0 = __fmaf_rn(xs[b + 0][c], wc, s0);
            s1 = __fmaf_rn(xs[b + 1][c], wc, s1);
            s2 = __fmaf_rn(xs[b + 2][c], wc, s2);
            s3 = __fmaf_rn(xs[b + 3][c], wc, s3);
        }
        g_Xp[d][f][b + 0][h] = __fadd_rn(s0, bias);
        g_Xp[d][f][b + 1][h] = __fadd_rn(s1, bias);
        g_Xp[d][f][b + 2][h] = __fadd_rn(s2, bias);
        g_Xp[d][f][b + 3][h] = __fadd_rn(s3, bias);
    }
}

// ---------------- 2) transpose Wr (+1 zero pad row) ----------------
__global__ void transpose_kernel(const float* __restrict__ Wr_fw, const float* __restrict__ Wr_bw)
{
    int idx = blockIdx.x * blockDim.x + threadIdx.x;
    int total = 2 * 257 * HN;
    if (idx >= total) return;
    int d = idx / (257 * HN);
    int r = idx % (257 * HN);
    int i = r / HN;
    int h = r % HN;
    const float* Wr = d ? Wr_bw : Wr_fw;
    g_WrT[d][i][h] = (i < HN) ? Wr[h * HN + i] : 0.0f;
}

// ---------------- 2b) transpose W_out into k-major float4 layout ----------------
__global__ void outT_kernel(const float* __restrict__ W_out)
{
    int idx = blockIdx.x * blockDim.x + threadIdx.x;   // over 128*64
    if (idx >= 128 * 64) return;
    int kq = idx >> 6, oo = idx & 63;
    const float4* W4 = (const float4*)W_out;           // [61][128] float4
    g_WoutT[kq][oo] = (oo < ON) ? __ldg(W4 + oo * 128 + kq)
                                : make_float4(0.f, 0.f, 0.f, 0.f);
}

// ---------------- 3) recurrence: 128 CTAs x 256 thr; 1 CTA = (d, batch pair), 2 chains/thread
// Pure __ldg gather (tiny smem -> full L1 for WrT); one direction per SM (<=1 CTA/SM).
__global__ void __launch_bounds__(256) recur_kernel(
    const float* __restrict__ tau_m_fw, const float* __restrict__ tau_adp_fw,
    const float* __restrict__ tau_m_bw, const float* __restrict__ tau_adp_bw,
    const float* __restrict__ br_fw,   const float* __restrict__ br_bw)
{
    int c  = blockIdx.x;           // 0..127
    int d  = c & 1;
    int bA = (c >> 1) * 2;
    int bB = bA + 1;
    int h = threadIdx.x;
    int warp = h >> 5, lane = h & 31;

    const float* tm = d ? tau_m_bw : tau_m_fw;
    const float* ta = d ? tau_adp_bw : tau_adp_fw;
    const float* brp = d ? br_bw : br_fw;
    float alpha = (float)exp((double)__fdiv_rn(-1.0f, tm[h]));
    float ro    = (float)exp((double)__fdiv_rn(-1.0f, ta[h]));
    float oma   = __fsub_rn(1.0f, alpha);
    float omro  = __fsub_rn(1.0f, ro);
    float br    = brp[h];

    const float* WrT = &g_WrT[d][0][0];

    float memA = 0.0f, spkA = 0.0f, badpA = 0.01f, bsumA = 0.0f, inpA = 0.0f;
    float memB = 0.0f, spkB = 0.0f, badpB = 0.01f, bsumB = 0.0f, inpB = 0.0f;

    __shared__ __align__(16) unsigned smaskA[8], smaskB[8];
    __shared__ __align__(16) unsigned short slistA[264], slistB[264];

    for (int t = 0; t < TN; t++) {
        int tm5 = t % 5;
        bool reload = d ? (t == 0 || tm5 == 1) : (tm5 == 0);
        if (reload) {
            int f = d ? ((200 - (t + 4) / 5) % 200) : (t / 5);
            inpA = g_Xp[d][f][bA][h];
            inpB = g_Xp[d][f][bB][h];
        }

        unsigned mA = __ballot_sync(0xffffffffu, spkA != 0.0f);
        unsigned mB = __ballot_sync(0xffffffffu, spkB != 0.0f);
        if (lane == 0) { smaskA[warp] = mA; smaskB[warp] = mB; }
        __syncthreads();   // S1: masks visible; also fences prior-step slist reads

        uint4 a0 = *(const uint4*)smaskA;
        uint4 a1 = *(const uint4*)(smaskA + 4);
        uint4 q0 = *(const uint4*)smaskB;
        uint4 q1 = *(const uint4*)(smaskB + 4);
        int cntA = __popc(a0.x) + __popc(a0.y) + __popc(a0.z) + __popc(a0.w)
                 + __popc(a1.x) + __popc(a1.y) + __popc(a1.z) + __popc(a1.w);
        int cntB = __popc(q0.x) + __popc(q0.y) + __popc(q0.z) + __popc(q0.w)
                 + __popc(q1.x) + __popc(q1.y) + __popc(q1.z) + __popc(q1.w);
        int nA = (cntA + 7) & ~7;
        int nB = (cntB + 7) & ~7;

        if (h < 16) {   // builders: threads 0..7 -> chain A words 0..7; 8..15 -> chain B
            unsigned wdA[8] = {a0.x, a0.y, a0.z, a0.w, a1.x, a1.y, a1.z, a1.w};
            unsigned wdB[8] = {q0.x, q0.y, q0.z, q0.w, q1.x, q1.y, q1.z, q1.w};
            int which = h >> 3, w = h & 7;
            const unsigned* wd = which ? wdB : wdA;
            unsigned short* sl = which ? slistB : slistA;
            int base = 0;
#pragma unroll
            for (int j = 0; j < 8; j++) if (j < w) base += __popc(wd[j]);
            unsigned mm = wd[w];
            int p = base;
            while (mm) {
                int bit = __ffs(mm) - 1;
                sl[p] = (unsigned short)(w * 32 + bit);
                p++; mm &= mm - 1;
            }
        }
        if (h >= cntA && h < nA) slistA[h] = (unsigned short)256;  // zero row sentinel
        if (h >= cntB && h < nB) slistB[h] = (unsigned short)256;
        __syncthreads();   // S2: lists visible

        // ---- dual-chain gather: up to 16 loads in flight; ascending per chain ----
        float rsumA = 0.0f, rsumB = 0.0f;
        int n = nA > nB ? nA : nB;
        for (int k = 0; k < n; k += 8) {
            bool doA = k < nA, doB = k < nB;
            float vA0, vA1, vA2, vA3, vA4, vA5, vA6, vA7;
            float vB0, vB1, vB2, vB3, vB4, vB5, vB6, vB7;
            if (doA) {
                uint4 u = *(const uint4*)(slistA + k);
                vA0 = __ldg(WrT + (u.x & 0xffff) * HN + h);
                vA1 = __ldg(WrT + (u.x >> 16)    * HN + h);
                vA2 = __ldg(WrT + (u.y & 0xffff) * HN + h);
                vA3 = __ldg(WrT + (u.y >> 16)    * HN + h);
                vA4 = __ldg(WrT + (u.z & 0xffff) * HN + h);
                vA5 = __ldg(WrT + (u.z >> 16)    * HN + h);
                vA6 = __ldg(WrT + (u.w & 0xffff) * HN + h);
                vA7 = __ldg(WrT + (u.w >> 16)    * HN + h);
            }
            if (doB) {
                uint4 u = *(const uint4*)(slistB + k);
                vB0 = __ldg(WrT + (u.x & 0xffff) * HN + h);
                vB1 = __ldg(WrT + (u.x >> 16)    * HN + h);
                vB2 = __ldg(WrT + (u.y & 0xffff) * HN + h);
                vB3 = __ldg(WrT + (u.y >> 16)    * HN + h);
                vB4 = __ldg(WrT + (u.z & 0xffff) * HN + h);
                vB5 = __ldg(WrT + (u.z >> 16)    * HN + h);
                vB6 = __ldg(WrT + (u.w & 0xffff) * HN + h);
                vB7 = __ldg(WrT + (u.w >> 16)    * HN + h);
            }
            if (doA) {
                rsumA = __fadd_rn(rsumA, vA0); rsumA = __fadd_rn(rsumA, vA1);
                rsumA = __fadd_rn(rsumA, vA2); rsumA = __fadd_rn(rsumA, vA3);
                rsumA = __fadd_rn(rsumA, vA4); rsumA = __fadd_rn(rsumA, vA5);
                rsumA = __fadd_rn(rsumA, vA6); rsumA = __fadd_rn(rsumA, vA7);
            }
            if (doB) {
                rsumB = __fadd_rn(rsumB, vB0); rsumB = __fadd_rn(rsumB, vB1);
                rsumB = __fadd_rn(rsumB, vB2); rsumB = __fadd_rn(rsumB, vB3);
                rsumB = __fadd_rn(rsumB, vB4); rsumB = __fadd_rn(rsumB, vB5);
                rsumB = __fadd_rn(rsumB, vB6); rsumB = __fadd_rn(rsumB, vB7);
            }
        }

        // ---- adaptive-LIF x2; exact JAX association, NO FMA contraction ----
        {
            float din = __fadd_rn(__fadd_rn(inpA, rsumA), br);
            badpA = __fadd_rn(__fmul_rn(ro, badpA), __fmul_rn(omro, spkA));
            float Bth = __fadd_rn(0.01f, __fmul_rn(1.8f, badpA));
            memA = __fsub_rn(__fadd_rn(__fmul_rn(memA, alpha), __fmul_rn(oma, din)),
                             __fmul_rn(Bth, spkA));
            spkA = (__fsub_rn(memA, Bth) > 0.0f) ? 1.0f : 0.0f;
            bsumA = __fadd_rn(bsumA, spkA);
        }
        {
            float din = __fadd_rn(__fadd_rn(inpB, rsumB), br);
            badpB = __fadd_rn(__fmul_rn(ro, badpB), __fmul_rn(omro, spkB));
            float Bth = __fadd_rn(0.01f, __fmul_rn(1.8f, badpB));
            memB = __fsub_rn(__fadd_rn(__fmul_rn(memB, alpha), __fmul_rn(oma, din)),
                             __fmul_rn(Bth, spkB));
            spkB = (__fsub_rn(memB, Bth) > 0.0f) ? 1.0f : 0.0f;
            bsumB = __fadd_rn(bsumB, spkB);
        }

        if (tm5 == 4) {
            int s = d ? (199 - t / 5) : (t / 5);
            g_block[s][bA][d * HN + h] = __fdiv_rn(bsumA, 5.0f);
            g_block[s][bB][d * HN + h] = __fdiv_rn(bsumB, 5.0f);
            bsumA = 0.0f; bsumB = 0.0f;
        }
    }
}

// ---------------- 4) output GEMM; x tile in smem (32KB), W via k-major L1 path ----------------
#define OUTMM_SMEM (16 * 128 * 16)
__global__ void __launch_bounds__(256) outmm_kernel(const float* __restrict__ b_out)
{
    extern __shared__ char sm_raw[];
    float4* xs4 = (float4*)sm_raw;                  // [16][128]

    int bt = blockIdx.x & 7;
    int s  = blockIdx.x >> 3;
    int tid = threadIdx.x;
    int o  = tid & 63;
    int bq = tid >> 6;      // 0..3 -> batches {bq, bq+4, bq+8, bq+12}

    const float4* gb4 = (const float4*)&g_block[s][bt * 16][0];
    for (int i = tid; i < 16 * 128; i += 256) xs4[i] = gb4[i];
    __syncthreads();

    float a0 = 0.f, a1 = 0.f, a2 = 0.f, a3 = 0.f;
    const float4* x0 = xs4 + (bq + 0) * 128;
    const float4* x1 = xs4 + (bq + 4) * 128;
    const float4* x2 = xs4 + (bq + 8) * 128;
    const float4* x3 = xs4 + (bq + 12) * 128;
#pragma unroll 4
    for (int kq = 0; kq < 128; kq++) {
        float4 wv = __ldg(&g_WoutT[kq][o]);    // lanes: contiguous 512B, L1-hot
        float4 v0 = x0[kq], v1 = x1[kq], v2 = x2[kq], v3 = x3[kq];
        a0 = __fmaf_rn(v0.x, wv.x, a0); a0 = __fmaf_rn(v0.y, wv.y, a0);
        a0 = __fmaf_rn(v0.z, wv.z, a0); a0 = __fmaf_rn(v0.w, wv.w, a0);
        a1 = __fmaf_rn(v1.x, wv.x, a1); a1 = __fmaf_rn(v1.y, wv.y, a1);
        a1 = __fmaf_rn(v1.z, wv.z, a1); a1 = __fmaf_rn(v1.w, wv.w, a1);
        a2 = __fmaf_rn(v2.x, wv.x, a2); a2 = __fmaf_rn(v2.y, wv.y, a2);
        a2 = __fmaf_rn(v2.z, wv.z, a2); a2 = __fmaf_rn(v2.w, wv.w, a2);
        a3 = __fmaf_rn(v3.x, wv.x, a3); a3 = __fmaf_rn(v3.y, wv.y, a3);
        a3 = __fmaf_rn(v3.z, wv.z, a3); a3 = __fmaf_rn(v3.w, wv.w, a3);
    }
    if (o < ON) {
        float bo = b_out[o];
        int bb = bt * 16 + bq;
        g_y[s][bb + 0][o]  = __fadd_rn(a0, bo);
        g_y[s][bb + 4][o]  = __fadd_rn(a1, bo);
        g_y[s][bb + 8][o]  = __fadd_rn(a2, bo);
        g_y[s][bb + 12][o] = __fadd_rn(a3, bo);
    }
}

// ---------------- 5) leaky-integrator scan over s ----------------
__global__ void scan_kernel(const float* __restrict__ tau_m_out)
{
    int idx = blockIdx.x * blockDim.x + threadIdx.x;
    if (idx >= BN * ON) return;
    int b = idx / ON, o = idx % ON;
    float a = (float)exp((double)__fdiv_rn(-1.0f, tau_m_out[o]));
    float omA = __fsub_rn(1.0f, a);
    float mem = 0.0f;
    for (int s = 0; s < SEQN; s++) {
        mem = __fadd_rn(__fmul_rn(mem, a), __fmul_rn(omA, g_y[s][b][o]));
        g_y[s][b][o] = mem;
    }
}

// ---------------- 6) log_softmax per (s,b) row ----------------
__global__ void __launch_bounds__(256) softmax_kernel(float* __restrict__ out)
{
    int row = blockIdx.x * (blockDim.x >> 5) + (threadIdx.x >> 5);
    if (row >= SEQN * BN) return;
    int lane = threadIdx.x & 31;
    const float* yr = &g_y[0][0][0] + row * ON;

    float v0 = (lane < ON)      ? yr[lane]      : -1e30f;
    float v1 = (lane + 32 < ON) ? yr[lane + 32] : -1e30f;
    float mx = fmaxf(v0, v1);
#pragma unroll
    for (int off = 16; off; off >>= 1) mx = fmaxf(mx, __shfl_xor_sync(0xffffffffu, mx, off));
    float e = ((lane < ON) ? expf(__fsub_rn(v0, mx)) : 0.0f)
            + ((lane + 32 < ON) ? expf(__fsub_rn(v1, mx)) : 0.0f);
#pragma unroll
    for (int off = 16; off; off >>= 1) e += __shfl_xor_sync(0xffffffffu, e, off);
    float lse = __fadd_rn(mx, logf(e));
    if (lane < ON)      out[row * ON + lane]      = __fsub_rn(v0, lse);
    if (lane + 32 < ON) out[row * ON + lane + 32] = __fsub_rn(v1, lse);
}

// ---------------- host launcher ----------------
extern "C" void kernel_launch(void* const* d_in, const int* in_sizes, int n_in,
                              void* d_out, int out_size)
{
    const float* x         = (const float*)d_in[0];
    const float* Wi_fw     = (const float*)d_in[1];
    const float* bi_fw     = (const float*)d_in[2];
    const float* Wr_fw     = (const float*)d_in[3];
    const float* br_fw     = (const float*)d_in[4];
    const float* tau_m_fw  = (const float*)d_in[5];
    const float* tau_adp_fw= (const float*)d_in[6];
    const float* Wi_bw     = (const float*)d_in[7];
    const float* bi_bw     = (const float*)d_in[8];
    const float* Wr_bw     = (const float*)d_in[9];
    const float* br_bw     = (const float*)d_in[10];
    const float* tau_m_bw  = (const float*)d_in[11];
    const float* tau_adp_bw= (const float*)d_in[12];
    const float* W_out     = (const float*)d_in[13];
    const float* b_out     = (const float*)d_in[14];
    const float* tau_m_out = (const float*)d_in[15];

    static int configured = 0;
    if (!configured) {
        cudaFuncSetAttribute(outmm_kernel, cudaFuncAttributeMaxDynamicSharedMemorySize, OUTMM_SMEM);
        cudaFuncSetAttribute(recur_kernel, cudaFuncAttributePreferredSharedMemoryCarveout, 0); // max L1
        configured = 1;
    }

    proj_kernel<<<2 * SEQN, 256>>>(x, Wi_fw, bi_fw, Wi_bw, bi_bw);                 // 1
    transpose_kernel<<<(2 * 257 * HN + 255) / 256, 256>>>(Wr_fw, Wr_bw);           // 2
    outT_kernel<<<(128 * 64 + 255) / 256, 256>>>(W_out);                           // 3
    recur_kernel<<<128, 256>>>(tau_m_fw, tau_adp_fw, tau_m_bw, tau_adp_bw,         // 4 (ncu slot)
                               br_fw, br_bw);
    outmm_kernel<<<SEQN * 8, 256, OUTMM_SMEM>>>(b_out);                            // 5
    scan_kernel<<<(BN * ON + 255) / 256, 256>>>(tau_m_out);                        // 6
    softmax_kernel<<<(SEQN * BN + 7) / 8, 256>>>((float*)d_out);                   // 7
}

// round 7
// speedup vs baseline: 1.7240x; 1.7240x over previous
#include <cuda_runtime.h>
#include <math.h>

#define HN   256
#define CINN 39
#define BN   128
#define SEQN 200
#define TN   1000
#define ON   61

// ---------------- scratch (device globals; no allocation allowed) ----------------
__device__ float g_Xp[2][SEQN][BN][HN];        // per-frame input projection + bi (NOT br)
__device__ float g_WrT[2][257][HN];            // WrT[d][i][h] = Wr_d[h][i]; row 256 = zeros
__device__ float g_block[SEQN][BN][2 * HN];    // 5-step block averages (merged fw|bw)
__device__ float g_y[SEQN][BN][ON];            // output-head pre/post scan values
__device__ float4 g_WoutT[128][64];            // W_out k-major: [kq][o] float4; o=61..63 zero

// ---------------- 1) input projection ----------------
__global__ void __launch_bounds__(256) proj_kernel(
    const float* __restrict__ x,
    const float* __restrict__ Wi_fw, const float* __restrict__ bi_fw,
    const float* __restrict__ Wi_bw, const float* __restrict__ bi_bw)
{
    int blk = blockIdx.x;          // 0..399
    int d = blk & 1;
    int f = blk >> 1;
    const float* Wi = d ? Wi_bw : Wi_fw;
    const float* bi = d ? bi_bw : bi_fw;
    int h = threadIdx.x;

    __shared__ float xs[BN][CINN + 1];
    for (int i = h; i < BN * CINN; i += blockDim.x) {
        int b = i / CINN, c = i % CINN;
        xs[b][c] = x[(b * SEQN + f) * CINN + c];
    }
    __syncthreads();

    float w[CINN];
#pragma unroll
    for (int c = 0; c < CINN; c++) w[c] = Wi[h * CINN + c];
    float bias = bi[h];

    for (int b = 0; b < BN; b += 4) {
        float s0 = 0.0f, s1 = 0.0f, s2 = 0.0f, s3 = 0.0f;
#pragma unroll
        for (int c = 0; c < CINN; c++) {
            float wc = w[c];
            s0 = __fmaf_rn(xs[b + 0][c], wc, s0);
            s1 = __fmaf_rn(xs[b + 1][c], wc, s1);
            s2 = __fmaf_rn(xs[b + 2][c], wc, s2);
            s3 = __fmaf_rn(xs[b + 3][c], wc, s3);
        }
        g_Xp[d][f][b + 0][h] = __fadd_rn(s0, bias);
        g_Xp[d][f][b + 1][h] = __fadd_rn(s1, bias);
        g_Xp[d][f][b + 2][h] = __fadd_rn(s2, bias);
        g_Xp[d][f][b + 3][h] = __fadd_rn(s3, bias);
    }
}

// ---------------- 2) transpose Wr (+1 zero pad row) ----------------
__global__ void transpose_kernel(const float* __restrict__ Wr_fw, const float* __restrict__ Wr_bw)
{
    int idx = blockIdx.x * blockDim.x + threadIdx.x;
    int total = 2 * 257 * HN;
    if (idx >= total) return;
    int d = idx / (257 * HN);
    int r = idx % (257 * HN);
    int i = r / HN;
    int h = r % HN;
    const float* Wr = d ? Wr_bw : Wr_fw;
    g_WrT[d][i][h] = (i < HN) ? Wr[h * HN + i] : 0.0f;
}

// ---------------- 2b) transpose W_out into k-major float4 layout ----------------
__global__ void outT_kernel(const float* __restrict__ W_out)
{
    int idx = blockIdx.x * blockDim.x + threadIdx.x;   // over 128*64
    if (idx >= 128 * 64) return;
    int kq = idx >> 6, oo = idx & 63;
    const float4* W4 = (const float4*)W_out;           // [61][128] float4
    g_WoutT[kq][oo] = (oo < ON) ? __ldg(W4 + oo * 128 + kq)
                                : make_float4(0.f, 0.f, 0.f, 0.f);
}

// ---------------- 3) recurrence: R3 structure (256 CTAs x 256 thr, 1 chain/CTA), unroll-16 ----
// bid and bid+148 share an SM and have equal parity (148 even) -> same direction -> one 257KB
// WrT working set per SM L1. Two CTAs/SM mutually hide serial phases + L2-miss stalls.
__global__ void __launch_bounds__(256, 2) recur_kernel(
    const float* __restrict__ tau_m_fw, const float* __restrict__ tau_adp_fw,
    const float* __restrict__ tau_m_bw, const float* __restrict__ tau_adp_bw,
    const float* __restrict__ br_fw,   const float* __restrict__ br_bw)
{
    int d = blockIdx.x & 1;
    int b = blockIdx.x >> 1;
    int h = threadIdx.x;
    int warp = h >> 5, lane = h & 31;

    const float* tm = d ? tau_m_bw : tau_m_fw;
    const float* ta = d ? tau_adp_bw : tau_adp_fw;
    const float* brp = d ? br_bw : br_fw;
    float alpha = (float)exp((double)__fdiv_rn(-1.0f, tm[h]));
    float ro    = (float)exp((double)__fdiv_rn(-1.0f, ta[h]));
    float oma   = __fsub_rn(1.0f, alpha);
    float omro  = __fsub_rn(1.0f, ro);
    float br    = brp[h];

    const float* WrT = &g_WrT[d][0][0];

    float mem = 0.0f, spk = 0.0f, badp = 0.01f;
    float blocksum = 0.0f;
    float inp = 0.0f;

    __shared__ __align__(16) unsigned smask[8];
    __shared__ __align__(16) unsigned short slist[256];

    unsigned lanelt = (lane == 0) ? 0u : (0xffffffffu >> (32 - lane));

    for (int t = 0; t < TN; t++) {
        int tm5 = t % 5;
        bool reload = d ? (t == 0 || tm5 == 1) : (tm5 == 0);
        if (reload) {
            int f = d ? ((200 - (t + 4) / 5) % 200) : (t / 5);
            inp = g_Xp[d][f][b][h];
        }

        // ---- build active-neuron list: fully parallel (each spiker stores its own index) ----
        unsigned m = __ballot_sync(0xffffffffu, spk != 0.0f);
        if (lane == 0) smask[warp] = m;
        __syncthreads();   // S1: masks visible; also fences prior-step slist reads vs writes

        uint4 ma = *(const uint4*)smask;
        uint4 mb = *(const uint4*)(smask + 4);
        int pc[8] = {__popc(ma.x), __popc(ma.y), __popc(ma.z), __popc(ma.w),
                     __popc(mb.x), __popc(mb.y), __popc(mb.z), __popc(mb.w)};
        int cnt = 0, base = 0;
#pragma unroll
        for (int w = 0; w < 8; w++) {
            if (w < warp) base += pc[w];
            cnt += pc[w];
        }
        if (spk != 0.0f) {
            int pos = base + __popc(m & lanelt);
            slist[pos] = (unsigned short)h;
        }
        int cnt_pad = (cnt + 15) & ~15;           // pad to 16 with exact-zero sentinel rows
        if (h >= cnt && h < cnt_pad) slist[h] = (unsigned short)256;
        __syncthreads();   // S2: list visible

        // ---- gather: 16 loads in flight, ascending index (bit-identical summation) ----
        float rsum = 0.0f;
        for (int k = 0; k < cnt_pad; k += 16) {
            uint4 u0 = *(const uint4*)(slist + k);
            uint4 u1 = *(const uint4*)(slist + k + 8);
            float v0  = __ldg(WrT + (u0.x & 0xffff) * HN + h);
            float v1  = __ldg(WrT + (u0.x >> 16)    * HN + h);
            float v2  = __ldg(WrT + (u0.y & 0xffff) * HN + h);
            float v3  = __ldg(WrT + (u0.y >> 16)    * HN + h);
            float v4  = __ldg(WrT + (u0.z & 0xffff) * HN + h);
            float v5  = __ldg(WrT + (u0.z >> 16)    * HN + h);
            float v6  = __ldg(WrT + (u0.w & 0xffff) * HN + h);
            float v7  = __ldg(WrT + (u0.w >> 16)    * HN + h);
            float v8  = __ldg(WrT + (u1.x & 0xffff) * HN + h);
            float v9  = __ldg(WrT + (u1.x >> 16)    * HN + h);
            float v10 = __ldg(WrT + (u1.y & 0xffff) * HN + h);
            float v11 = __ldg(WrT + (u1.y >> 16)    * HN + h);
            float v12 = __ldg(WrT + (u1.z & 0xffff) * HN + h);
            float v13 = __ldg(WrT + (u1.z >> 16)    * HN + h);
            float v14 = __ldg(WrT + (u1.w & 0xffff) * HN + h);
            float v15 = __ldg(WrT + (u1.w >> 16)    * HN + h);
            rsum = __fadd_rn(rsum, v0);  rsum = __fadd_rn(rsum, v1);
            rsum = __fadd_rn(rsum, v2);  rsum = __fadd_rn(rsum, v3);
            rsum = __fadd_rn(rsum, v4);  rsum = __fadd_rn(rsum, v5);
            rsum = __fadd_rn(rsum, v6);  rsum = __fadd_rn(rsum, v7);
            rsum = __fadd_rn(rsum, v8);  rsum = __fadd_rn(rsum, v9);
            rsum = __fadd_rn(rsum, v10); rsum = __fadd_rn(rsum, v11);
            rsum = __fadd_rn(rsum, v12); rsum = __fadd_rn(rsum, v13);
            rsum = __fadd_rn(rsum, v14); rsum = __fadd_rn(rsum, v15);
        }

        // ---- adaptive-LIF update; exact JAX association, NO FMA contraction ----
        float din = __fadd_rn(__fadd_rn(inp, rsum), br);
        badp = __fadd_rn(__fmul_rn(ro, badp), __fmul_rn(omro, spk));
        float Bth = __fadd_rn(0.01f, __fmul_rn(1.8f, badp));
        mem = __fsub_rn(__fadd_rn(__fmul_rn(mem, alpha), __fmul_rn(oma, din)),
                        __fmul_rn(Bth, spk));
        spk = (__fsub_rn(mem, Bth) > 0.0f) ? 1.0f : 0.0f;

        blocksum = __fadd_rn(blocksum, spk);
        if (tm5 == 4) {
            int s = d ? (199 - t / 5) : (t / 5);
            g_block[s][b][d * HN + h] = __fdiv_rn(blocksum, 5.0f);
            blocksum = 0.0f;
        }
    }
}

// ---------------- 4) output GEMM; x tile in smem (32KB), W via k-major L1 path ----------------
#define OUTMM_SMEM (16 * 128 * 16)
__global__ void __launch_bounds__(256) outmm_kernel(const float* __restrict__ b_out)
{
    extern __shared__ char sm_raw[];
    float4* xs4 = (float4*)sm_raw;                  // [16][128]

    int bt = blockIdx.x & 7;
    int s  = blockIdx.x >> 3;
    int tid = threadIdx.x;
    int o  = tid & 63;
    int bq = tid >> 6;      // 0..3 -> batches {bq, bq+4, bq+8, bq+12}

    const float4* gb4 = (const float4*)&g_block[s][bt * 16][0];
    for (int i = tid; i < 16 * 128; i += 256) xs4[i] = gb4[i];
    __syncthreads();

    float a0 = 0.f, a1 = 0.f, a2 = 0.f, a3 = 0.f;
    const float4* x0 = xs4 + (bq + 0) * 128;
    const float4* x1 = xs4 + (bq + 4) * 128;
    const float4* x2 = xs4 + (bq + 8) * 128;
    const float4* x3 = xs4 + (bq + 12) * 128;
#pragma unroll 4
    for (int kq = 0; kq < 128; kq++) {
        float4 wv = __ldg(&g_WoutT[kq][o]);    // lanes: contiguous 512B, L1-hot
        float4 v0 = x0[kq], v1 = x1[kq], v2 = x2[kq], v3 = x3[kq];
        a0 = __fmaf_rn(v0.x, wv.x, a0); a0 = __fmaf_rn(v0.y, wv.y, a0);
        a0 = __fmaf_rn(v0.z, wv.z, a0); a0 = __fmaf_rn(v0.w, wv.w, a0);
        a1 = __fmaf_rn(v1.x, wv.x, a1); a1 = __fmaf_rn(v1.y, wv.y, a1);
        a1 = __fmaf_rn(v1.z, wv.z, a1); a1 = __fmaf_rn(v1.w, wv.w, a1);
        a2 = __fmaf_rn(v2.x, wv.x, a2); a2 = __fmaf_rn(v2.y, wv.y, a2);
        a2 = __fmaf_rn(v2.z, wv.z, a2); a2 = __fmaf_rn(v2.w, wv.w, a2);
        a3 = __fmaf_rn(v3.x, wv.x, a3); a3 = __fmaf_rn(v3.y, wv.y, a3);
        a3 = __fmaf_rn(v3.z, wv.z, a3); a3 = __fmaf_rn(v3.w, wv.w, a3);
    }
    if (o < ON) {
        float bo = b_out[o];
        int bb = bt * 16 + bq;
        g_y[s][bb + 0][o]  = __fadd_rn(a0, bo);
        g_y[s][bb + 4][o]  = __fadd_rn(a1, bo);
        g_y[s][bb + 8][o]  = __fadd_rn(a2, bo);
        g_y[s][bb + 12][o] = __fadd_rn(a3, bo);
    }
}

// ---------------- 5) leaky-integrator scan over s ----------------
__global__ void scan_kernel(const float* __restrict__ tau_m_out)
{
    int idx = blockIdx.x * blockDim.x + threadIdx.x;
    if (idx >= BN * ON) return;
    int b = idx / ON, o = idx % ON;
    float a = (float)exp((double)__fdiv_rn(-1.0f, tau_m_out[o]));
    float omA = __fsub_rn(1.0f, a);
    float mem = 0.0f;
    for (int s = 0; s < SEQN; s++) {
        mem = __fadd_rn(__fmul_rn(mem, a), __fmul_rn(omA, g_y[s][b][o]));
        g_y[s][b][o] = mem;
    }
}

// ---------------- 6) log_softmax per (s,b) row ----------------
__global__ void __launch_bounds__(256) softmax_kernel(float* __restrict__ out)
{
    int row = blockIdx.x * (blockDim.x >> 5) + (threadIdx.x >> 5);
    if (row >= SEQN * BN) return;
    int lane = threadIdx.x & 31;
    const float* yr = &g_y[0][0][0] + row * ON;

    float v0 = (lane < ON)      ? yr[lane]      : -1e30f;
    float v1 = (lane + 32 < ON) ? yr[lane + 32] : -1e30f;
    float mx = fmaxf(v0, v1);
#pragma unroll
    for (int off = 16; off; off >>= 1) mx = fmaxf(mx, __shfl_xor_sync(0xffffffffu, mx, off));
    float e = ((lane < ON) ? expf(__fsub_rn(v0, mx)) : 0.0f)
            + ((lane + 32 < ON) ? expf(__fsub_rn(v1, mx)) : 0.0f);
#pragma unroll
    for (int off = 16; off; off >>= 1) e += __shfl_xor_sync(0xffffffffu, e, off);
    float lse = __fadd_rn(mx, logf(e));
    if (lane < ON)      out[row * ON + lane]      = __fsub_rn(v0, lse);
    if (lane + 32 < ON) out[row * ON + lane + 32] = __fsub_rn(v1, lse);
}

// ---------------- host launcher ----------------
extern "C" void kernel_launch(void* const* d_in, const int* in_sizes, int n_in,
                              void* d_out, int out_size)
{
    const float* x         = (const float*)d_in[0];
    const float* Wi_fw     = (const float*)d_in[1];
    const float* bi_fw     = (const float*)d_in[2];
    const float* Wr_fw     = (const float*)d_in[3];
    const float* br_fw     = (const float*)d_in[4];
    const float* tau_m_fw  = (const float*)d_in[5];
    const float* tau_adp_fw= (const float*)d_in[6];
    const float* Wi_bw     = (const float*)d_in[7];
    const float* bi_bw     = (const float*)d_in[8];
    const float* Wr_bw     = (const float*)d_in[9];
    const float* br_bw     = (const float*)d_in[10];
    const float* tau_m_bw  = (const float*)d_in[11];
    const float* tau_adp_bw= (const float*)d_in[12];
    const float* W_out     = (const float*)d_in[13];
    const float* b_out     = (const float*)d_in[14];
    const float* tau_m_out = (const float*)d_in[15];

    static int configured = 0;
    if (!configured) {
        cudaFuncSetAttribute(outmm_kernel, cudaFuncAttributeMaxDynamicSharedMemorySize, OUTMM_SMEM);
        cudaFuncSetAttribute(recur_kernel, cudaFuncAttributePreferredSharedMemoryCarveout, 0); // max L1
        configured = 1;
    }

    proj_kernel<<<2 * SEQN, 256>>>(x, Wi_fw, bi_fw, Wi_bw, bi_bw);                 // 1
    transpose_kernel<<<(2 * 257 * HN + 255) / 256, 256>>>(Wr_fw, Wr_bw);           // 2
    outT_kernel<<<(128 * 64 + 255) / 256, 256>>>(W_out);                           // 3
    recur_kernel<<<2 * BN, 256>>>(tau_m_fw, tau_adp_fw, tau_m_bw, tau_adp_bw,      // 4 (ncu slot)
                                  br_fw, br_bw);
    outmm_kernel<<<SEQN * 8, 256, OUTMM_SMEM>>>(b_out);                            // 5
    scan_kernel<<<(BN * ON + 255) / 256, 256>>>(tau_m_out);                        // 6
    softmax_kernel<<<(SEQN * BN + 7) / 8, 256>>>((float*)d_out);                   // 7
}

// round 8
// speedup vs baseline: 2.0634x; 1.1968x over previous
#include <cuda_runtime.h>
#include <math.h>

#define HN   256
#define CINN 39
#define BN   128
#define SEQN 200
#define TN   1000
#define ON   61

typedef unsigned long long ull;

// packed 2xfp32 add, per-lane round-to-nearest: bit-identical to two __fadd_rn
__device__ __forceinline__ ull addf32x2(ull a, ull b) {
    ull r;
    asm("add.rn.f32x2 %0, %1, %2;" : "=l"(r) : "l"(a), "l"(b));
    return r;
}

// ---------------- scratch (device globals; no allocation allowed) ----------------
__device__ float g_Xp[2][SEQN][BN][HN];                    // input projection + bi (NOT br)
__device__ __align__(16) float g_WrT[2][257][HN];          // WrT[d][i][h]; row 256 = zeros
__device__ float g_block[SEQN][BN][2 * HN];                // 5-step block averages
__device__ float g_y[SEQN][BN][ON];                        // output-head values
__device__ float4 g_WoutT[128][64];                        // W_out k-major; o=61..63 zero

// ---------------- 1) input projection ----------------
__global__ void __launch_bounds__(256) proj_kernel(
    const float* __restrict__ x,
    const float* __restrict__ Wi_fw, const float* __restrict__ bi_fw,
    const float* __restrict__ Wi_bw, const float* __restrict__ bi_bw)
{
    int blk = blockIdx.x;          // 0..399
    int d = blk & 1;
    int f = blk >> 1;
    const float* Wi = d ? Wi_bw : Wi_fw;
    const float* bi = d ? bi_bw : bi_fw;
    int h = threadIdx.x;

    __shared__ float xs[BN][CINN + 1];
    for (int i = h; i < BN * CINN; i += blockDim.x) {
        int b = i / CINN, c = i % CINN;
        xs[b][c] = x[(b * SEQN + f) * CINN + c];
    }
    __syncthreads();

    float w[CINN];
#pragma unroll
    for (int c = 0; c < CINN; c++) w[c] = Wi[h * CINN + c];
    float bias = bi[h];

    for (int b = 0; b < BN; b += 4) {
        float s0 = 0.0f, s1 = 0.0f, s2 = 0.0f, s3 = 0.0f;
#pragma unroll
        for (int c = 0; c < CINN; c++) {
            float wc = w[c];
            s0 = __fmaf_rn(xs[b + 0][c], wc, s0);
            s1 = __fmaf_rn(xs[b + 1][c], wc, s1);
            s2 = __fmaf_rn(xs[b + 2][c], wc, s2);
            s3 = __fmaf_rn(xs[b + 3][c], wc, s3);
        }
        g_Xp[d][f][b + 0][h] = __fadd_rn(s0, bias);
        g_Xp[d][f][b + 1][h] = __fadd_rn(s1, bias);
        g_Xp[d][f][b + 2][h] = __fadd_rn(s2, bias);
        g_Xp[d][f][b + 3][h] = __fadd_rn(s3, bias);
    }
}

// ---------------- 2) transpose Wr (+1 zero pad row) ----------------
__global__ void transpose_kernel(const float* __restrict__ Wr_fw, const float* __restrict__ Wr_bw)
{
    int idx = blockIdx.x * blockDim.x + threadIdx.x;
    int total = 2 * 257 * HN;
    if (idx >= total) return;
    int d = idx / (257 * HN);
    int r = idx % (257 * HN);
    int i = r / HN;
    int h = r % HN;
    const float* Wr = d ? Wr_bw : Wr_fw;
    g_WrT[d][i][h] = (i < HN) ? Wr[h * HN + i] : 0.0f;
}

// ---------------- 2b) transpose W_out into k-major float4 layout ----------------
__global__ void outT_kernel(const float* __restrict__ W_out)
{
    int idx = blockIdx.x * blockDim.x + threadIdx.x;   // over 128*64
    if (idx >= 128 * 64) return;
    int kq = idx >> 6, oo = idx & 63;
    const float4* W4 = (const float4*)W_out;           // [61][128] float4
    g_WoutT[kq][oo] = (oo < ON) ? __ldg(W4 + oo * 128 + kq)
                                : make_float4(0.f, 0.f, 0.f, 0.f);
}

// ---------------- 3) recurrence: 256 CTAs x 128 thr; 2 neurons/thread, packed f32x2 gather --
// bid and bid+148 share an SM with equal parity -> same direction -> one WrT per SM L1.
__global__ void __launch_bounds__(128, 2) recur_kernel(
    const float* __restrict__ tau_m_fw, const float* __restrict__ tau_adp_fw,
    const float* __restrict__ tau_m_bw, const float* __restrict__ tau_adp_bw,
    const float* __restrict__ br_fw,   const float* __restrict__ br_bw)
{
    int d = blockIdx.x & 1;
    int b = blockIdx.x >> 1;
    int tid = threadIdx.x;             // 0..127
    int warp = tid >> 5, lane = tid & 31;
    int n0 = 2 * tid;                  // even neuron
    int n1 = n0 + 1;                   // odd neuron

    const float* tm = d ? tau_m_bw : tau_m_fw;
    const float* ta = d ? tau_adp_bw : tau_adp_fw;
    const float* brp = d ? br_bw : br_fw;
    float alpha0 = (float)exp((double)__fdiv_rn(-1.0f, tm[n0]));
    float alpha1 = (float)exp((double)__fdiv_rn(-1.0f, tm[n1]));
    float ro0    = (float)exp((double)__fdiv_rn(-1.0f, ta[n0]));
    float ro1    = (float)exp((double)__fdiv_rn(-1.0f, ta[n1]));
    float oma0   = __fsub_rn(1.0f, alpha0), oma1 = __fsub_rn(1.0f, alpha1);
    float omro0  = __fsub_rn(1.0f, ro0),    omro1 = __fsub_rn(1.0f, ro1);
    float br0    = brp[n0], br1 = brp[n1];

    const float* Wcol = &g_WrT[d][0][0] + n0;   // column base for this thread's neuron pair

    float mem0 = 0.0f, spk0 = 0.0f, badp0 = 0.01f, bsum0 = 0.0f, inp0 = 0.0f;
    float mem1 = 0.0f, spk1 = 0.0f, badp1 = 0.01f, bsum1 = 0.0f, inp1 = 0.0f;

    __shared__ __align__(16) unsigned smask[8];     // [warp][even/odd]
    __shared__ __align__(16) int slist[256];

    unsigned lanelt = (lane == 0) ? 0u : (0xffffffffu >> (32 - lane));

    for (int t = 0; t < TN; t++) {
        int tm5 = t % 5;
        bool reload = d ? (t == 0 || tm5 == 1) : (tm5 == 0);
        if (reload) {
            int f = d ? ((200 - (t + 4) / 5) % 200) : (t / 5);
            inp0 = g_Xp[d][f][b][n0];
            inp1 = g_Xp[d][f][b][n1];
        }

        // ---- build active-neuron list (ascending neuron index) ----
        bool s0 = (spk0 != 0.0f), s1 = (spk1 != 0.0f);
        unsigned m0 = __ballot_sync(0xffffffffu, s0);
        unsigned m1 = __ballot_sync(0xffffffffu, s1);
        if (lane == 0) { smask[warp * 2] = m0; smask[warp * 2 + 1] = m1; }
        __syncthreads();   // S1: masks visible; fences prior-step slist reads vs writes

        uint4 ma = *(const uint4*)smask;          // warps 0,1
        uint4 mb = *(const uint4*)(smask + 4);    // warps 2,3
        int pw0 = __popc(ma.x) + __popc(ma.y);    // warp 0 total
        int pw1 = __popc(ma.z) + __popc(ma.w);
        int pw2 = __popc(mb.x) + __popc(mb.y);
        int pw3 = __popc(mb.z) + __popc(mb.w);
        int cnt = pw0 + pw1 + pw2 + pw3;
        int base = 0;
        if (warp > 0) base += pw0;
        if (warp > 1) base += pw1;
        if (warp > 2) base += pw2;

        int p0 = base + __popc(m0 & lanelt) + __popc(m1 & lanelt);
        if (s0) slist[p0] = n0;
        if (s1) slist[p0 + (s0 ? 1 : 0)] = n1;
        int cnt_pad = (cnt + 15) & ~15;
        if (tid < cnt_pad - cnt) slist[cnt + tid] = 256;   // zero-row sentinels
        __syncthreads();   // S2: list visible

        // ---- packed gather: 16 rows/iter, one LDG.64 + one add.rn.f32x2 per row ----
        ull rsum = 0ull;   // lanes: (+0.0f, +0.0f)
        for (int k = 0; k < cnt_pad; k += 16) {
            int4 ia = *(const int4*)(slist + k);
            int4 ib = *(const int4*)(slist + k + 4);
            int4 ic = *(const int4*)(slist + k + 8);
            int4 id = *(const int4*)(slist + k + 12);
            ull v0  = __ldg((const ull*)(Wcol + ia.x * HN));
            ull v1  = __ldg((const ull*)(Wcol + ia.y * HN));
            ull v2  = __ldg((const ull*)(Wcol + ia.z * HN));
            ull v3  = __ldg((const ull*)(Wcol + ia.w * HN));
            ull v4  = __ldg((const ull*)(Wcol + ib.x * HN));
            ull v5  = __ldg((const ull*)(Wcol + ib.y * HN));
            ull v6  = __ldg((const ull*)(Wcol + ib.z * HN));
            ull v7  = __ldg((const ull*)(Wcol + ib.w * HN));
            ull v8  = __ldg((const ull*)(Wcol + ic.x * HN));
            ull v9  = __ldg((const ull*)(Wcol + ic.y * HN));
            ull v10 = __ldg((const ull*)(Wcol + ic.z * HN));
            ull v11 = __ldg((const ull*)(Wcol + ic.w * HN));
            ull v12 = __ldg((const ull*)(Wcol + id.x * HN));
            ull v13 = __ldg((const ull*)(Wcol + id.y * HN));
            ull v14 = __ldg((const ull*)(Wcol + id.z * HN));
            ull v15 = __ldg((const ull*)(Wcol + id.w * HN));
            rsum = addf32x2(rsum, v0);  rsum = addf32x2(rsum, v1);
            rsum = addf32x2(rsum, v2);  rsum = addf32x2(rsum, v3);
            rsum = addf32x2(rsum, v4);  rsum = addf32x2(rsum, v5);
            rsum = addf32x2(rsum, v6);  rsum = addf32x2(rsum, v7);
            rsum = addf32x2(rsum, v8);  rsum = addf32x2(rsum, v9);
            rsum = addf32x2(rsum, v10); rsum = addf32x2(rsum, v11);
            rsum = addf32x2(rsum, v12); rsum = addf32x2(rsum, v13);
            rsum = addf32x2(rsum, v14); rsum = addf32x2(rsum, v15);
        }
        float rs0 = __uint_as_float((unsigned)(rsum & 0xffffffffull));
        float rs1 = __uint_as_float((unsigned)(rsum >> 32));

        // ---- adaptive-LIF x2; exact JAX association, NO FMA contraction ----
        {
            float din = __fadd_rn(__fadd_rn(inp0, rs0), br0);
            badp0 = __fadd_rn(__fmul_rn(ro0, badp0), __fmul_rn(omro0, spk0));
            float Bth = __fadd_rn(0.01f, __fmul_rn(1.8f, badp0));
            mem0 = __fsub_rn(__fadd_rn(__fmul_rn(mem0, alpha0), __fmul_rn(oma0, din)),
                             __fmul_rn(Bth, spk0));
            spk0 = (__fsub_rn(mem0, Bth) > 0.0f) ? 1.0f : 0.0f;
            bsum0 = __fadd_rn(bsum0, spk0);
        }
        {
            float din = __fadd_rn(__fadd_rn(inp1, rs1), br1);
            badp1 = __fadd_rn(__fmul_rn(ro1, badp1), __fmul_rn(omro1, spk1));
            float Bth = __fadd_rn(0.01f, __fmul_rn(1.8f, badp1));
            mem1 = __fsub_rn(__fadd_rn(__fmul_rn(mem1, alpha1), __fmul_rn(oma1, din)),
                             __fmul_rn(Bth, spk1));
            spk1 = (__fsub_rn(mem1, Bth) > 0.0f) ? 1.0f : 0.0f;
            bsum1 = __fadd_rn(bsum1, spk1);
        }

        if (tm5 == 4) {
            int s = d ? (199 - t / 5) : (t / 5);
            g_block[s][b][d * HN + n0] = __fdiv_rn(bsum0, 5.0f);
            g_block[s][b][d * HN + n1] = __fdiv_rn(bsum1, 5.0f);
            bsum0 = 0.0f; bsum1 = 0.0f;
        }
    }
}

// ---------------- 4) output GEMM; x tile in smem (32KB), W via k-major L1 path ----------------
#define OUTMM_SMEM (16 * 128 * 16)
__global__ void __launch_bounds__(256) outmm_kernel(const float* __restrict__ b_out)
{
    extern __shared__ char sm_raw[];
    float4* xs4 = (float4*)sm_raw;                  // [16][128]

    int bt = blockIdx.x & 7;
    int s  = blockIdx.x >> 3;
    int tid = threadIdx.x;
    int o  = tid & 63;
    int bq = tid >> 6;      // 0..3 -> batches {bq, bq+4, bq+8, bq+12}

    const float4* gb4 = (const float4*)&g_block[s][bt * 16][0];
    for (int i = tid; i < 16 * 128; i += 256) xs4[i] = gb4[i];
    __syncthreads();

    float a0 = 0.f, a1 = 0.f, a2 = 0.f, a3 = 0.f;
    const float4* x0 = xs4 + (bq + 0) * 128;
    const float4* x1 = xs4 + (bq + 4) * 128;
    const float4* x2 = xs4 + (bq + 8) * 128;
    const float4* x3 = xs4 + (bq + 12) * 128;
#pragma unroll 4
    for (int kq = 0; kq < 128; kq++) {
        float4 wv = __ldg(&g_WoutT[kq][o]);    // lanes: contiguous 512B, L1-hot
        float4 v0 = x0[kq], v1 = x1[kq], v2 = x2[kq], v3 = x3[kq];
        a0 = __fmaf_rn(v0.x, wv.x, a0); a0 = __fmaf_rn(v0.y, wv.y, a0);
        a0 = __fmaf_rn(v0.z, wv.z, a0); a0 = __fmaf_rn(v0.w, wv.w, a0);
        a1 = __fmaf_rn(v1.x, wv.x, a1); a1 = __fmaf_rn(v1.y, wv.y, a1);
        a1 = __fmaf_rn(v1.z, wv.z, a1); a1 = __fmaf_rn(v1.w, wv.w, a1);
        a2 = __fmaf_rn(v2.x, wv.x, a2); a2 = __fmaf_rn(v2.y, wv.y, a2);
        a2 = __fmaf_rn(v2.z, wv.z, a2); a2 = __fmaf_rn(v2.w, wv.w, a2);
        a3 = __fmaf_rn(v3.x, wv.x, a3); a3 = __fmaf_rn(v3.y, wv.y, a3);
        a3 = __fmaf_rn(v3.z, wv.z, a3); a3 = __fmaf_rn(v3.w, wv.w, a3);
    }
    if (o < ON) {
        float bo = b_out[o];
        int bb = bt * 16 + bq;
        g_y[s][bb + 0][o]  = __fadd_rn(a0, bo);
        g_y[s][bb + 4][o]  = __fadd_rn(a1, bo);
        g_y[s][bb + 8][o]  = __fadd_rn(a2, bo);
        g_y[s][bb + 12][o] = __fadd_rn(a3, bo);
    }
}

// ---------------- 5) leaky-integrator scan over s ----------------
__global__ void scan_kernel(const float* __restrict__ tau_m_out)
{
    int idx = blockIdx.x * blockDim.x + threadIdx.x;
    if (idx >= BN * ON) return;
    int b = idx / ON, o = idx % ON;
    float a = (float)exp((double)__fdiv_rn(-1.0f, tau_m_out[o]));
    float omA = __fsub_rn(1.0f, a);
    float mem = 0.0f;
    for (int s = 0; s < SEQN; s++) {
        mem = __fadd_rn(__fmul_rn(mem, a), __fmul_rn(omA, g_y[s][b][o]));
        g_y[s][b][o] = mem;
    }
}

// ---------------- 6) log_softmax per (s,b) row ----------------
__global__ void __launch_bounds__(256) softmax_kernel(float* __restrict__ out)
{
    int row = blockIdx.x * (blockDim.x >> 5) + (threadIdx.x >> 5);
    if (row >= SEQN * BN) return;
    int lane = threadIdx.x & 31;
    const float* yr = &g_y[0][0][0] + row * ON;

    float v0 = (lane < ON)      ? yr[lane]      : -1e30f;
    float v1 = (lane + 32 < ON) ? yr[lane + 32] : -1e30f;
    float mx = fmaxf(v0, v1);
#pragma unroll
    for (int off = 16; off; off >>= 1) mx = fmaxf(mx, __shfl_xor_sync(0xffffffffu, mx, off));
    float e = ((lane < ON) ? expf(__fsub_rn(v0, mx)) : 0.0f)
            + ((lane + 32 < ON) ? expf(__fsub_rn(v1, mx)) : 0.0f);
#pragma unroll
    for (int off = 16; off; off >>= 1) e += __shfl_xor_sync(0xffffffffu, e, off);
    float lse = __fadd_rn(mx, logf(e));
    if (lane < ON)      out[row * ON + lane]      = __fsub_rn(v0, lse);
    if (lane + 32 < ON) out[row * ON + lane + 32] = __fsub_rn(v1, lse);
}

// ---------------- host launcher ----------------
extern "C" void kernel_launch(void* const* d_in, const int* in_sizes, int n_in,
                              void* d_out, int out_size)
{
    const float* x         = (const float*)d_in[0];
    const float* Wi_fw     = (const float*)d_in[1];
    const float* bi_fw     = (const float*)d_in[2];
    const float* Wr_fw     = (const float*)d_in[3];
    const float* br_fw     = (const float*)d_in[4];
    const float* tau_m_fw  = (const float*)d_in[5];
    const float* tau_adp_fw= (const float*)d_in[6];
    const float* Wi_bw     = (const float*)d_in[7];
    const float* bi_bw     = (const float*)d_in[8];
    const float* Wr_bw     = (const float*)d_in[9];
    const float* br_bw     = (const float*)d_in[10];
    const float* tau_m_bw  = (const float*)d_in[11];
    const float* tau_adp_bw= (const float*)d_in[12];
    const float* W_out     = (const float*)d_in[13];
    const float* b_out     = (const float*)d_in[14];
    const float* tau_m_out = (const float*)d_in[15];

    static int configured = 0;
    if (!configured) {
        cudaFuncSetAttribute(outmm_kernel, cudaFuncAttributeMaxDynamicSharedMemorySize, OUTMM_SMEM);
        cudaFuncSetAttribute(recur_kernel, cudaFuncAttributePreferredSharedMemoryCarveout, 0); // max L1
        configured = 1;
    }

    proj_kernel<<<2 * SEQN, 256>>>(x, Wi_fw, bi_fw, Wi_bw, bi_bw);                 // 1
    transpose_kernel<<<(2 * 257 * HN + 255) / 256, 256>>>(Wr_fw, Wr_bw);           // 2
    outT_kernel<<<(128 * 64 + 255) / 256, 256>>>(W_out);                           // 3
    recur_kernel<<<2 * BN, 128>>>(tau_m_fw, tau_adp_fw, tau_m_bw, tau_adp_bw,      // 4 (ncu slot)
                                  br_fw, br_bw);
    outmm_kernel<<<SEQN * 8, 256, OUTMM_SMEM>>>(b_out);                            // 5
    scan_kernel<<<(BN * ON + 255) / 256, 256>>>(tau_m_out);                        // 6
    softmax_kernel<<<(SEQN * BN + 7) / 8, 256>>>((float*)d_out);                   // 7
}